// round 1
// baseline (speedup 1.0000x reference)
#include <cuda_runtime.h>
#include <cstdint>

// ---- config: jax threefry partitionable mode (default True since jax 0.4.36) ----
#define JAX_PARTITIONABLE 1

#define Bn   32
#define Gn   50
#define Hn   64
#define Wn   64
#define An   9
#define HWn  4096
#define KAn  36864
#define NINn 18624
#define HALFN 9312

// anchor tables (derived exactly from reference _generate_anchors, base 16, ratios .5/1/2, scales 8/16/32)
__constant__ int   c_ixmin[9]={6,11,23,4,8,16,3,5,11};
__constant__ int   c_ixmax[9]={57,52,40,59,55,47,60,58,52};
__constant__ int   c_iymin[9]={3,6,12,4,8,16,5,11,22};
__constant__ int   c_iymax[9]={60,57,51,59,55,47,58,52,41};
__constant__ float c_ax1[9]={-84.f,-176.f,-360.f,-56.f,-120.f,-248.f,-36.f,-80.f,-168.f};
__constant__ float c_ay1[9]={-40.f,-88.f,-184.f,-56.f,-120.f,-248.f,-80.f,-168.f,-344.f};
__constant__ float c_ax2[9]={99.f,191.f,375.f,71.f,135.f,263.f,51.f,95.f,183.f};
__constant__ float c_ay2[9]={55.f,103.f,199.f,71.f,135.f,263.f,95.f,183.f,359.f};
__constant__ float c_aw[9] ={184.f,368.f,736.f,128.f,256.f,512.f,88.f,176.f,352.f};
__constant__ float c_ah[9] ={96.f,192.f,384.f,128.f,256.f,512.f,176.f,352.f,704.f};
__constant__ float c_area[9]={17664.f,70656.f,282624.f,16384.f,65536.f,262144.f,15488.f,61952.f,247808.f};

// scratch (static device globals; no allocation)
__device__ unsigned      g_keys[Bn][4];      // kf0,kf1,kb0,kb1 per image
__device__ float         g_gtmax[Bn*Gn];
__device__ float         g_maxov[Bn*KAn];    // a-major: b*KA + a*HW + iy*W + ix
__device__ int           g_arg[Bn*KAn];
__device__ unsigned char g_cls[Bn*KAn];      // 0=bg,1=fg,2=ignore,3=outside
__device__ int           g_cnt[Bn*2];        // [b][0]=nfg,[b][1]=nbg
__device__ unsigned      g_thrV[Bn*2];       // 23-bit threshold value (0xFFFFFFFF = keep all)
__device__ int           g_thrN[Bn*2];       // tie cutoff compact index

// ---------------- Threefry-2x32 (bit-exact with jax) ----------------
__device__ __forceinline__ void tf2x32(unsigned k0, unsigned k1, unsigned x0, unsigned x1,
                                       unsigned& o0, unsigned& o1) {
    unsigned k2 = k0 ^ k1 ^ 0x1BD11BDAu;
    x0 += k0; x1 += k1;
#define TFR(r) { x0 += x1; x1 = (x1 << (r)) | (x1 >> (32 - (r))); x1 ^= x0; }
    TFR(13) TFR(15) TFR(26) TFR(6)   x0 += k1; x1 += k2 + 1u;
    TFR(17) TFR(29) TFR(16) TFR(24)  x0 += k2; x1 += k0 + 2u;
    TFR(13) TFR(15) TFR(26) TFR(6)   x0 += k0; x1 += k1 + 3u;
    TFR(17) TFR(29) TFR(16) TFR(24)  x0 += k1; x1 += k2 + 4u;
    TFR(13) TFR(15) TFR(26) TFR(6)   x0 += k2; x1 += k0 + 5u;
#undef TFR
    o0 = x0; o1 = x1;
}

// uniform bits for compact index n (reproduces jax.random.uniform bit stream)
__device__ __forceinline__ unsigned ubits(unsigned k0, unsigned k1, int n) {
#if JAX_PARTITIONABLE
    unsigned y0, y1;
    tf2x32(k0, k1, 0u, (unsigned)n, y0, y1);
    return y0 ^ y1;
#else
    unsigned y0, y1;
    if (n < HALFN) { tf2x32(k0, k1, (unsigned)n, (unsigned)(n + HALFN), y0, y1); return y0; }
    else           { tf2x32(k0, k1, (unsigned)(n - HALFN), (unsigned)n, y0, y1); return y1; }
#endif
}

// compact (inside-subset) index of anchor (iy,ix,a), ordering = full index (iy*W+ix)*A + a
__device__ __forceinline__ int compact_index(int iy, int ix, int a) {
    int n = 0;
#pragma unroll
    for (int j = 0; j < 9; j++) {
        int cy = min(iy, c_iymax[j] + 1) - c_iymin[j]; cy = max(cy, 0);
        int cx = c_ixmax[j] - c_ixmin[j] + 1;
        n += cy * cx;
        if (iy >= c_iymin[j] && iy <= c_iymax[j]) {
            int px = min(ix, c_ixmax[j] + 1) - c_ixmin[j]; px = max(px, 0);
            n += px;
            if (j < a && ix >= c_ixmin[j] && ix <= c_ixmax[j]) n += 1;
        }
    }
    return n;
}

// exact-IEEE IoU replicating reference op order (no FMA contraction)
__device__ __forceinline__ float iou_f(float ax1, float ay1, float ax2, float ay2, float areaa,
                                       float gx1, float gy1, float gx2, float gy2, float areag) {
    float iw = __fadd_rn(__fsub_rn(fminf(ax2, gx2), fmaxf(ax1, gx1)), 1.0f); iw = fmaxf(iw, 0.0f);
    float ih = __fadd_rn(__fsub_rn(fminf(ay2, gy2), fmaxf(ay1, gy1)), 1.0f); ih = fmaxf(ih, 0.0f);
    float inter = __fmul_rn(iw, ih);
    return __fdiv_rn(inter, __fsub_rn(__fadd_rn(areaa, areag), inter));
}

// ---------------- kernels ----------------
__global__ void k_init() {
    int t = threadIdx.x;
    if (t < Bn) {
        unsigned f0, f1, q0, q1;
#if JAX_PARTITIONABLE
        unsigned b0, b1;
        tf2x32(0u, 42u, 0u, (unsigned)t, b0, b1);         // keys[t] = split(key(42),32)[t]
        tf2x32(b0, b1, 0u, 0u, f0, f1);                   // kf
        tf2x32(b0, b1, 0u, 1u, q0, q1);                   // kb
        g_keys[t][0] = f0; g_keys[t][1] = f1; g_keys[t][2] = q0; g_keys[t][3] = q1;
#else
        unsigned b0, b1, o0, o1;
        int j0 = 2 * t, j1 = 2 * t + 1;
        if (j0 < 32) { tf2x32(0u, 42u, (unsigned)j0, (unsigned)(j0 + 32), o0, o1); b0 = o0; }
        else         { tf2x32(0u, 42u, (unsigned)(j0 - 32), (unsigned)j0, o0, o1); b0 = o1; }
        if (j1 < 32) { tf2x32(0u, 42u, (unsigned)j1, (unsigned)(j1 + 32), o0, o1); b1 = o0; }
        else         { tf2x32(0u, 42u, (unsigned)(j1 - 32), (unsigned)j1, o0, o1); b1 = o1; }
        unsigned p0, p1;
        tf2x32(b0, b1, 0u, 2u, p0, p1);   // out0 (lane0) -> kf[0], out2 (lane1) -> kb[0]
        tf2x32(b0, b1, 1u, 3u, f0, f1);   // out1 (lane0) -> kf[1], out3 (lane1) -> kb[1]
        g_keys[t][0] = p0; g_keys[t][1] = f0; g_keys[t][2] = p1; g_keys[t][3] = f1;
#endif
    }
    if (t < Bn * 2) g_cnt[t] = 0;
}

__global__ void __launch_bounds__(256) k_gtmax(const float* __restrict__ gt) {
    int blk = blockIdx.x;
    int b = blk / Gn, g = blk - b * Gn;
    const float* gb = gt + (size_t)(b * Gn + g) * 4;
    float gx1 = gb[0], gy1 = gb[1], gx2 = gb[2], gy2 = gb[3];
    float gw = __fadd_rn(__fsub_rn(gx2, gx1), 1.0f);
    float gh = __fadd_rn(__fsub_rn(gy2, gy1), 1.0f);
    float areag = __fmul_rn(gw, gh);
    float best = 0.0f;
    for (int j = threadIdx.x; j < KAn; j += 256) {
        int a = j / HWn; int r = j - a * HWn; int iy = r >> 6; int ix = r & 63;
        if (ix < c_ixmin[a] || ix > c_ixmax[a] || iy < c_iymin[a] || iy > c_iymax[a]) continue;
        float sx = (float)(ix << 4), sy = (float)(iy << 4);
        float ov = iou_f(c_ax1[a] + sx, c_ay1[a] + sy, c_ax2[a] + sx, c_ay2[a] + sy, c_area[a],
                         gx1, gy1, gx2, gy2, areag);
        best = fmaxf(best, ov);
    }
    __shared__ float red[256];
    red[threadIdx.x] = best;
    __syncthreads();
    for (int s = 128; s > 0; s >>= 1) {
        if (threadIdx.x < s) red[threadIdx.x] = fmaxf(red[threadIdx.x], red[threadIdx.x + s]);
        __syncthreads();
    }
    if (threadIdx.x == 0) g_gtmax[b * Gn + g] = red[0];
}

__global__ void __launch_bounds__(256) k_anchor(const float* __restrict__ gt) {
    __shared__ float sgt[Gn * 4];
    __shared__ float sgm[Gn];
    __shared__ int scnt[2];
    int b = blockIdx.y;
    int t = threadIdx.x;
    if (t < Gn * 4) sgt[t] = gt[(size_t)b * Gn * 4 + t];
    if (t >= 200 && t < 250) sgm[t - 200] = g_gtmax[b * Gn + (t - 200)];
    if (t < 2) scnt[t] = 0;
    __syncthreads();
    int j = blockIdx.x * 256 + t;                 // a-major index
    int a = j / HWn; int r = j - a * HWn; int iy = r >> 6; int ix = r & 63;
    unsigned char cls = 3;
    if (!(ix < c_ixmin[a] || ix > c_ixmax[a] || iy < c_iymin[a] || iy > c_iymax[a])) {
        float sx = (float)(ix << 4), sy = (float)(iy << 4);
        float ax1 = c_ax1[a] + sx, ay1 = c_ay1[a] + sy, ax2 = c_ax2[a] + sx, ay2 = c_ay2[a] + sy;
        float areaa = c_area[a];
        float best = -1.0f; int arg = 0; bool hit = false;
        for (int g = 0; g < Gn; g++) {
            float gx1 = sgt[g * 4 + 0], gy1 = sgt[g * 4 + 1], gx2 = sgt[g * 4 + 2], gy2 = sgt[g * 4 + 3];
            float gw = __fadd_rn(__fsub_rn(gx2, gx1), 1.0f);
            float gh = __fadd_rn(__fsub_rn(gy2, gy1), 1.0f);
            float areag = __fmul_rn(gw, gh);
            float ov = iou_f(ax1, ay1, ax2, ay2, areaa, gx1, gy1, gx2, gy2, areag);
            if (ov > best) { best = ov; arg = g; }
            float gm = sgm[g];
            hit = hit || (ov == gm && gm > 0.0f);
        }
        cls = (best >= 0.7f || hit) ? (unsigned char)1
            : ((best < 0.3f && !hit) ? (unsigned char)0 : (unsigned char)2);
        g_maxov[(size_t)b * KAn + j] = best;
        g_arg[(size_t)b * KAn + j] = arg;
        if (cls < 2) atomicAdd(&scnt[cls == 1 ? 0 : 1], 1);
    }
    g_cls[(size_t)b * KAn + j] = cls;
    __syncthreads();
    if (t < 2) atomicAdd(&g_cnt[b * 2 + t], scnt[t]);
}

// block-wide: find bin containing k-th (1-indexed) element; writes *s_bin, *s_below (count strictly below bin)
__device__ void find_kth(unsigned* hist, int per, unsigned k, unsigned* wsum,
                         int* s_bin, unsigned* s_below, int tid) {
    int base = tid * per;
    unsigned mysum = 0;
    for (int x = 0; x < per; x++) mysum += hist[base + x];
    unsigned lane = tid & 31, wid = tid >> 5;
    unsigned inc = mysum;
#pragma unroll
    for (int off = 1; off < 32; off <<= 1) {
        unsigned nv = __shfl_up_sync(0xffffffffu, inc, off);
        if (lane >= off) inc += nv;
    }
    if (lane == 31) wsum[wid] = inc;
    __syncthreads();
    if (wid == 0) {
        unsigned w = wsum[lane];
        unsigned iw = w;
#pragma unroll
        for (int off = 1; off < 32; off <<= 1) {
            unsigned nv = __shfl_up_sync(0xffffffffu, iw, off);
            if (lane >= off) iw += nv;
        }
        wsum[lane] = iw - w;
    }
    __syncthreads();
    unsigned run = wsum[wid] + (inc - mysum);
    for (int x = 0; x < per; x++) {
        unsigned h = hist[base + x];
        if (run < k && k <= run + h) { *s_bin = base + x; *s_below = run; }
        run += h;
    }
    __syncthreads();
}

__global__ void __launch_bounds__(1024) k_select() {
    __shared__ unsigned hist[4096];
    __shared__ unsigned wsum[32];
    __shared__ int s_bin; __shared__ unsigned s_below;
    __shared__ int s_list[4096]; __shared__ int s_cnt; __shared__ int s_cut;
    int bc = blockIdx.x; int b = bc >> 1; int c = bc & 1;   // c=0 fg, c=1 bg
    int tid = threadIdx.x;
    int nfg = g_cnt[b * 2 + 0], nbg = g_cnt[b * 2 + 1];
    int m = c ? nbg : nfg;
    unsigned k = c ? (unsigned)(256 - min(nfg, 128)) : 128u;
    if ((unsigned)m <= k) {
        if (tid == 0) { g_thrV[bc] = 0xFFFFFFFFu; g_thrN[bc] = 0x7FFFFFFF; }
        return;
    }
    unsigned key0 = g_keys[b][c * 2 + 0], key1 = g_keys[b][c * 2 + 1];
    unsigned char tcls = c ? (unsigned char)0 : (unsigned char)1;
    const unsigned char* cls = g_cls + (size_t)b * KAn;

    // pass 1: top-12-bit histogram of v = bits>>9
    for (int x = tid; x < 4096; x += 1024) hist[x] = 0;
    __syncthreads();
    for (int j = tid; j < KAn; j += 1024) {
        if (cls[j] != tcls) continue;
        int a = j / HWn, r = j - a * HWn, iy = r >> 6, ix = r & 63;
        int n = compact_index(iy, ix, a);
        unsigned v = ubits(key0, key1, n) >> 9;
        atomicAdd(&hist[v >> 11], 1u);
    }
    __syncthreads();
    find_kth(hist, 4, k, wsum, &s_bin, &s_below, tid);
    int T = s_bin; unsigned below1 = s_below;
    __syncthreads();

    // pass 2: low-11-bit histogram within bin T
    for (int x = tid; x < 2048; x += 1024) hist[x] = 0;
    __syncthreads();
    for (int j = tid; j < KAn; j += 1024) {
        if (cls[j] != tcls) continue;
        int a = j / HWn, r = j - a * HWn, iy = r >> 6, ix = r & 63;
        int n = compact_index(iy, ix, a);
        unsigned v = ubits(key0, key1, n) >> 9;
        if ((int)(v >> 11) == T) atomicAdd(&hist[v & 2047], 1u);
    }
    __syncthreads();
    find_kth(hist, 2, k - below1, wsum, &s_bin, &s_below, tid);
    unsigned V = ((unsigned)T << 11) | (unsigned)s_bin;
    unsigned cntLess = below1 + s_below;
    int R = (int)(k - cntLess);       // #ties to keep (>=1)
    __syncthreads();

    // pass 3: resolve ties at exact value V by compact-index order (stable argsort)
    if (tid == 0) { s_cnt = 0; s_cut = 0x7FFFFFFF; }
    __syncthreads();
    for (int j = tid; j < KAn; j += 1024) {
        if (cls[j] != tcls) continue;
        int a = j / HWn, r = j - a * HWn, iy = r >> 6, ix = r & 63;
        int n = compact_index(iy, ix, a);
        unsigned v = ubits(key0, key1, n) >> 9;
        if (v == V) { int p = atomicAdd(&s_cnt, 1); if (p < 4096) s_list[p] = n; }
    }
    __syncthreads();
    int E = min(s_cnt, 4096);
    if (R < E) {
        for (int e = tid; e < E; e += 1024) {
            int nv = s_list[e]; int rk = 0;
            for (int f = 0; f < E; f++) rk += (s_list[f] < nv);
            if (rk == R - 1) s_cut = nv;
        }
    }
    __syncthreads();
    if (tid == 0) { g_thrV[bc] = V; g_thrN[bc] = s_cut; }
}

__global__ void __launch_bounds__(256) k_final(const float* __restrict__ gt, float* __restrict__ out) {
    int b = blockIdx.y;
    int j = blockIdx.x * 256 + threadIdx.x;       // a-major
    int a = j / HWn; int r = j - a * HWn; int iy = r >> 6; int ix = r & 63;
    float label = -1.0f;
    float t0 = 0.f, t1 = 0.f, t2 = 0.f, t3 = 0.f;
    unsigned char cls = g_cls[(size_t)b * KAn + j];
    if (cls < 2) {
        int n = compact_index(iy, ix, a);
        int c = cls ? 0 : 1;
        unsigned v = ubits(g_keys[b][c * 2], g_keys[b][c * 2 + 1], n) >> 9;
        unsigned V = g_thrV[b * 2 + c]; int cut = g_thrN[b * 2 + c];
        bool keep = (v < V) || (v == V && n <= cut);
        if (cls == 1) {
            if (keep) {
                label = 1.0f;
                int arg = g_arg[(size_t)b * KAn + j];
                const float* gb = gt + (size_t)(b * Gn + arg) * 4;
                float gx1 = gb[0], gy1 = gb[1], gx2 = gb[2], gy2 = gb[3];
                float gw = __fadd_rn(__fsub_rn(gx2, gx1), 1.0f);
                float gh = __fadd_rn(__fsub_rn(gy2, gy1), 1.0f);
                float gcx = __fadd_rn(gx1, __fmul_rn(0.5f, __fsub_rn(gw, 1.0f)));
                float gcy = __fadd_rn(gy1, __fmul_rn(0.5f, __fsub_rn(gh, 1.0f)));
                float sx = (float)(ix << 4), sy = (float)(iy << 4);
                float aw = c_aw[a], ah = c_ah[a];
                float acx = __fadd_rn(__fadd_rn(c_ax1[a], sx), __fmul_rn(0.5f, __fsub_rn(aw, 1.0f)));
                float acy = __fadd_rn(__fadd_rn(c_ay1[a], sy), __fmul_rn(0.5f, __fsub_rn(ah, 1.0f)));
                t0 = __fdiv_rn(__fsub_rn(gcx, acx), aw);
                t1 = __fdiv_rn(__fsub_rn(gcy, acy), ah);
                t2 = logf(__fdiv_rn(gw, aw));
                t3 = logf(__fdiv_rn(gh, ah));
            }
        } else {
            label = keep ? 0.0f : -1.0f;
        }
    }
    // labels: [B, A, H, W]
    out[(size_t)b * An * HWn + (size_t)a * HWn + r] = label;
    // reg: [B, A*4, H, W] right after labels
    float* reg = out + (size_t)Bn * An * HWn;
    size_t rb = (size_t)b * An * 4 * HWn + (size_t)(a * 4) * HWn + r;
    reg[rb] = t0;
    reg[rb + HWn] = t1;
    reg[rb + 2 * HWn] = t2;
    reg[rb + 3 * HWn] = t3;
}

extern "C" void kernel_launch(void* const* d_in, const int* in_sizes, int n_in,
                              void* d_out, int out_size) {
    (void)in_sizes; (void)n_in; (void)out_size;
    const float* gt = (const float*)d_in[0];
    float* out = (float*)d_out;
    k_init<<<1, 256>>>();
    k_gtmax<<<Bn * Gn, 256>>>(gt);
    k_anchor<<<dim3(KAn / 256, Bn), 256>>>(gt);
    k_select<<<Bn * 2, 1024>>>();
    k_final<<<dim3(KAn / 256, Bn), 256>>>(gt, out);
}

// round 3
// speedup vs baseline: 3.2225x; 3.2225x over previous
#include <cuda_runtime.h>
#include <cstdint>

#define JAX_PARTITIONABLE 1

#define Bn   32
#define Gn   50
#define Hn   64
#define Wn   64
#define An   9
#define HWn  4096
#define KAn  36864
#define NINn 18624
#define HALFN 9312
#define CAP  18624

__constant__ int   c_ixmin[9]={6,11,23,4,8,16,3,5,11};
__constant__ int   c_ixmax[9]={57,52,40,59,55,47,60,58,52};
__constant__ int   c_iymin[9]={3,6,12,4,8,16,5,11,22};
__constant__ int   c_iymax[9]={60,57,51,59,55,47,58,52,41};
__constant__ float c_ax1[9]={-84.f,-176.f,-360.f,-56.f,-120.f,-248.f,-36.f,-80.f,-168.f};
__constant__ float c_ay1[9]={-40.f,-88.f,-184.f,-56.f,-120.f,-248.f,-80.f,-168.f,-344.f};
__constant__ float c_ax2[9]={99.f,191.f,375.f,71.f,135.f,263.f,51.f,95.f,183.f};
__constant__ float c_ay2[9]={55.f,103.f,199.f,71.f,135.f,263.f,95.f,183.f,359.f};
__constant__ float c_aw[9] ={184.f,368.f,736.f,128.f,256.f,512.f,88.f,176.f,352.f};
__constant__ float c_ah[9] ={96.f,192.f,384.f,128.f,256.f,512.f,176.f,352.f,704.f};
__constant__ float c_area[9]={17664.f,70656.f,282624.f,16384.f,65536.f,262144.f,15488.f,61952.f,247808.f};

// scratch
__device__ unsigned           g_keys[Bn][4];
__device__ unsigned long long g_key64[Bn*KAn];   // (ov_bits<<32)|(63-g)
__device__ unsigned char      g_hit[Bn*KAn];
__device__ unsigned char      g_cls[Bn*KAn];     // 0=bg,1=fg,2=ignore,3=outside
__device__ unsigned           g_v[Bn*KAn];       // 23-bit uniform payload (bits>>9), cls<2 only
__device__ int                g_cnt[Bn*2];       // [b][0]=nfg,[b][1]=nbg
__device__ unsigned           g_lv[Bn*2*CAP];    // compacted v list per (b,c)
__device__ int                g_ln[Bn*2*CAP];    // compacted n list per (b,c)
__device__ unsigned           g_thrV[Bn*2];
__device__ int                g_thrN[Bn*2];

// ---------------- Threefry-2x32 (bit-exact with jax) ----------------
__device__ __forceinline__ void tf2x32(unsigned k0, unsigned k1, unsigned x0, unsigned x1,
                                       unsigned& o0, unsigned& o1) {
    unsigned k2 = k0 ^ k1 ^ 0x1BD11BDAu;
    x0 += k0; x1 += k1;
#define TFR(r) { x0 += x1; x1 = (x1 << (r)) | (x1 >> (32 - (r))); x1 ^= x0; }
    TFR(13) TFR(15) TFR(26) TFR(6)   x0 += k1; x1 += k2 + 1u;
    TFR(17) TFR(29) TFR(16) TFR(24)  x0 += k2; x1 += k0 + 2u;
    TFR(13) TFR(15) TFR(26) TFR(6)   x0 += k0; x1 += k1 + 3u;
    TFR(17) TFR(29) TFR(16) TFR(24)  x0 += k1; x1 += k2 + 4u;
    TFR(13) TFR(15) TFR(26) TFR(6)   x0 += k2; x1 += k0 + 5u;
#undef TFR
    o0 = x0; o1 = x1;
}

__device__ __forceinline__ unsigned ubits(unsigned k0, unsigned k1, int n) {
#if JAX_PARTITIONABLE
    unsigned y0, y1;
    tf2x32(k0, k1, 0u, (unsigned)n, y0, y1);
    return y0 ^ y1;
#else
    unsigned y0, y1;
    if (n < HALFN) { tf2x32(k0, k1, (unsigned)n, (unsigned)(n + HALFN), y0, y1); return y0; }
    else           { tf2x32(k0, k1, (unsigned)(n - HALFN), (unsigned)n, y0, y1); return y1; }
#endif
}

__device__ __forceinline__ int compact_index(int iy, int ix, int a) {
    int n = 0;
#pragma unroll
    for (int j = 0; j < 9; j++) {
        int cy = min(iy, c_iymax[j] + 1) - c_iymin[j]; cy = max(cy, 0);
        int cx = c_ixmax[j] - c_ixmin[j] + 1;
        n += cy * cx;
        if (iy >= c_iymin[j] && iy <= c_iymax[j]) {
            int px = min(ix, c_ixmax[j] + 1) - c_ixmin[j]; px = max(px, 0);
            n += px;
            if (j < a && ix >= c_ixmin[j] && ix <= c_ixmax[j]) n += 1;
        }
    }
    return n;
}

__device__ __forceinline__ float iou_f(float ax1, float ay1, float ax2, float ay2, float areaa,
                                       float gx1, float gy1, float gx2, float gy2, float areag) {
    float iw = __fadd_rn(__fsub_rn(fminf(ax2, gx2), fmaxf(ax1, gx1)), 1.0f); iw = fmaxf(iw, 0.0f);
    float ih = __fadd_rn(__fsub_rn(fminf(ay2, gy2), fmaxf(ay1, gy1)), 1.0f); ih = fmaxf(ih, 0.0f);
    float inter = __fmul_rn(iw, ih);
    return __fdiv_rn(inter, __fsub_rn(__fadd_rn(areaa, areag), inter));
}

// ---------------- kernels ----------------
__global__ void k_init() {
    int t = threadIdx.x;
    if (t < Bn) {
        unsigned f0, f1, q0, q1, b0, b1;
        tf2x32(0u, 42u, 0u, (unsigned)t, b0, b1);
        tf2x32(b0, b1, 0u, 0u, f0, f1);
        tf2x32(b0, b1, 0u, 1u, q0, q1);
        g_keys[t][0] = f0; g_keys[t][1] = f1; g_keys[t][2] = q0; g_keys[t][3] = q1;
    }
    if (t < Bn * 2) g_cnt[t] = 0;
}

__global__ void __launch_bounds__(256) k_clear() {
    int i = blockIdx.x * 256 + threadIdx.x;
    g_key64[i] = 63ull;   // ov=0, arg=0
    g_hit[i] = 0;
}

// conservative window bounds for anchor type a vs gt box
__device__ __forceinline__ void win(int a, float gx1, float gy1, float gx2, float gy2,
                                    int& xlo, int& xhi, int& ylo, int& yhi) {
    xlo = max(c_ixmin[a], (int)floorf((gx1 - 1.0f - c_ax2[a]) * 0.0625f));
    xhi = min(c_ixmax[a], (int)ceilf((gx2 + 1.0f - c_ax1[a]) * 0.0625f));
    ylo = max(c_iymin[a], (int)floorf((gy1 - 1.0f - c_ay2[a]) * 0.0625f));
    yhi = min(c_iymax[a], (int)ceilf((gy2 + 1.0f - c_ay1[a]) * 0.0625f));
}

// one block per (b,g): pass A computes per-anchor atomicMax keys + this gt's max,
// then (after block reduce) pass B re-walks the window and flags ov==gt_max hits.
__global__ void __launch_bounds__(256) k_gtpass(const float* __restrict__ gt) {
    int blk = blockIdx.x;
    int b = blk / Gn, g = blk - b * Gn;
    const float* gb = gt + (size_t)(b * Gn + g) * 4;
    float gx1 = gb[0], gy1 = gb[1], gx2 = gb[2], gy2 = gb[3];
    float gw = __fadd_rn(__fsub_rn(gx2, gx1), 1.0f);
    float gh = __fadd_rn(__fsub_rn(gy2, gy1), 1.0f);
    float areag = __fmul_rn(gw, gh);
    float best = 0.0f;
    unsigned lowbits = (unsigned)(63 - g);
#pragma unroll
    for (int a = 0; a < 9; a++) {
        int xlo, xhi, ylo, yhi;
        win(a, gx1, gy1, gx2, gy2, xlo, xhi, ylo, yhi);
        int nx = xhi - xlo + 1, ny = yhi - ylo + 1;
        if (nx <= 0 || ny <= 0) continue;
        int tot = nx * ny;
        float ax1 = c_ax1[a], ay1 = c_ay1[a], ax2 = c_ax2[a], ay2 = c_ay2[a], areaa = c_area[a];
        for (int t = threadIdx.x; t < tot; t += 256) {
            int q = t / nx;
            int iy = ylo + q, ix = xlo + t - q * nx;
            float sx = (float)(ix << 4), sy = (float)(iy << 4);
            float ov = iou_f(ax1 + sx, ay1 + sy, ax2 + sx, ay2 + sy, areaa,
                             gx1, gy1, gx2, gy2, areag);
            if (ov > 0.0f) {
                best = fmaxf(best, ov);
                unsigned long long key = ((unsigned long long)__float_as_uint(ov) << 32) | lowbits;
                atomicMax(&g_key64[(size_t)b * KAn + a * HWn + (iy << 6) + ix], key);
            }
        }
    }
    __shared__ float red[256];
    red[threadIdx.x] = best;
    __syncthreads();
    for (int s = 128; s > 0; s >>= 1) {
        if (threadIdx.x < s) red[threadIdx.x] = fmaxf(red[threadIdx.x], red[threadIdx.x + s]);
        __syncthreads();
    }
    float gm = red[0];
    if (gm <= 0.0f) return;
    // pass B: flag anchors achieving this gt's max overlap
#pragma unroll
    for (int a = 0; a < 9; a++) {
        int xlo, xhi, ylo, yhi;
        win(a, gx1, gy1, gx2, gy2, xlo, xhi, ylo, yhi);
        int nx = xhi - xlo + 1, ny = yhi - ylo + 1;
        if (nx <= 0 || ny <= 0) continue;
        int tot = nx * ny;
        float ax1 = c_ax1[a], ay1 = c_ay1[a], ax2 = c_ax2[a], ay2 = c_ay2[a], areaa = c_area[a];
        for (int t = threadIdx.x; t < tot; t += 256) {
            int q = t / nx;
            int iy = ylo + q, ix = xlo + t - q * nx;
            float sx = (float)(ix << 4), sy = (float)(iy << 4);
            float ov = iou_f(ax1 + sx, ay1 + sy, ax2 + sx, ay2 + sy, areaa,
                             gx1, gy1, gx2, gy2, areag);
            if (ov == gm) g_hit[(size_t)b * KAn + a * HWn + (iy << 6) + ix] = 1;
        }
    }
}

__global__ void __launch_bounds__(256) k_label() {
    __shared__ int lcnt[2];
    __shared__ int lbase[2];
    int b = blockIdx.y;
    int t = threadIdx.x;
    if (t < 2) lcnt[t] = 0;
    __syncthreads();
    int j = blockIdx.x * 256 + t;       // a-major
    int a = j / HWn; int r = j - a * HWn; int iy = r >> 6; int ix = r & 63;
    unsigned char cls = 3;
    int c = 0, lp = 0, n = 0; unsigned v = 0;
    if (!(ix < c_ixmin[a] || ix > c_ixmax[a] || iy < c_iymin[a] || iy > c_iymax[a])) {
        unsigned long long key = g_key64[(size_t)b * KAn + j];
        float best = __uint_as_float((unsigned)(key >> 32));
        bool hit = g_hit[(size_t)b * KAn + j] != 0;
        cls = (hit || best >= 0.7f) ? (unsigned char)1
            : ((best < 0.3f) ? (unsigned char)0 : (unsigned char)2);
        if (cls < 2) {
            c = cls ? 0 : 1;
            n = compact_index(iy, ix, a);
            v = ubits(g_keys[b][c * 2], g_keys[b][c * 2 + 1], n) >> 9;
            g_v[(size_t)b * KAn + j] = v;
            lp = atomicAdd(&lcnt[c], 1);
        }
    }
    g_cls[(size_t)b * KAn + j] = cls;
    __syncthreads();
    if (t < 2) lbase[t] = lcnt[t] ? atomicAdd(&g_cnt[b * 2 + t], lcnt[t]) : 0;
    __syncthreads();
    if (cls < 2) {
        int p = (b * 2 + c) * CAP + lbase[c] + lp;
        g_lv[p] = v;
        g_ln[p] = n;
    }
}

__device__ void find_kth(unsigned* hist, int per, unsigned k, unsigned* wsum,
                         int* s_bin, unsigned* s_below, int tid) {
    int base = tid * per;
    unsigned mysum = 0;
    for (int x = 0; x < per; x++) mysum += hist[base + x];
    unsigned lane = tid & 31, wid = tid >> 5;
    unsigned inc = mysum;
#pragma unroll
    for (int off = 1; off < 32; off <<= 1) {
        unsigned nv = __shfl_up_sync(0xffffffffu, inc, off);
        if (lane >= off) inc += nv;
    }
    if (lane == 31) wsum[wid] = inc;
    __syncthreads();
    if (wid == 0) {
        unsigned w = wsum[lane];
        unsigned iw = w;
#pragma unroll
        for (int off = 1; off < 32; off <<= 1) {
            unsigned nv = __shfl_up_sync(0xffffffffu, iw, off);
            if (lane >= off) iw += nv;
        }
        wsum[lane] = iw - w;
    }
    __syncthreads();
    unsigned run = wsum[wid] + (inc - mysum);
    for (int x = 0; x < per; x++) {
        unsigned h = hist[base + x];
        if (run < k && k <= run + h) { *s_bin = base + x; *s_below = run; }
        run += h;
    }
    __syncthreads();
}

__global__ void __launch_bounds__(1024) k_select() {
    __shared__ unsigned hist[4096];
    __shared__ unsigned wsum[32];
    __shared__ int s_bin; __shared__ unsigned s_below;
    __shared__ int s_list[4096]; __shared__ int s_cnt; __shared__ int s_cut;
    int bc = blockIdx.x; int b = bc >> 1; int c = bc & 1;
    int tid = threadIdx.x;
    int nfg = g_cnt[b * 2 + 0], nbg = g_cnt[b * 2 + 1];
    int m = c ? nbg : nfg;
    unsigned k = c ? (unsigned)(256 - min(nfg, 128)) : 128u;
    if ((unsigned)m <= k) {
        if (tid == 0) { g_thrV[bc] = 0xFFFFFFFFu; g_thrN[bc] = 0x7FFFFFFF; }
        return;
    }
    const unsigned* lv = g_lv + (size_t)bc * CAP;
    const int* ln = g_ln + (size_t)bc * CAP;

    for (int x = tid; x < 4096; x += 1024) hist[x] = 0;
    __syncthreads();
    for (int i = tid; i < m; i += 1024) atomicAdd(&hist[lv[i] >> 11], 1u);
    __syncthreads();
    find_kth(hist, 4, k, wsum, &s_bin, &s_below, tid);
    int T = s_bin; unsigned below1 = s_below;
    __syncthreads();

    for (int x = tid; x < 2048; x += 1024) hist[x] = 0;
    __syncthreads();
    for (int i = tid; i < m; i += 1024) {
        unsigned v = lv[i];
        if ((int)(v >> 11) == T) atomicAdd(&hist[v & 2047], 1u);
    }
    __syncthreads();
    find_kth(hist, 2, k - below1, wsum, &s_bin, &s_below, tid);
    unsigned V = ((unsigned)T << 11) | (unsigned)s_bin;
    unsigned cntLess = below1 + s_below;
    int R = (int)(k - cntLess);
    __syncthreads();

    if (tid == 0) { s_cnt = 0; s_cut = 0x7FFFFFFF; }
    __syncthreads();
    for (int i = tid; i < m; i += 1024) {
        if (lv[i] == V) { int p = atomicAdd(&s_cnt, 1); if (p < 4096) s_list[p] = ln[i]; }
    }
    __syncthreads();
    int E = min(s_cnt, 4096);
    if (R < E) {
        for (int e = tid; e < E; e += 1024) {
            int nv = s_list[e]; int rk = 0;
            for (int f = 0; f < E; f++) rk += (s_list[f] < nv);
            if (rk == R - 1) s_cut = nv;
        }
    }
    __syncthreads();
    if (tid == 0) { g_thrV[bc] = V; g_thrN[bc] = s_cut; }
}

__global__ void __launch_bounds__(256) k_final(const float* __restrict__ gt, float* __restrict__ out) {
    int b = blockIdx.y;
    int j = blockIdx.x * 256 + threadIdx.x;   // a-major
    int a = j / HWn; int r = j - a * HWn; int iy = r >> 6; int ix = r & 63;
    float label = -1.0f;
    float t0 = 0.f, t1 = 0.f, t2 = 0.f, t3 = 0.f;
    unsigned char cls = g_cls[(size_t)b * KAn + j];
    if (cls < 2) {
        int n = compact_index(iy, ix, a);
        int c = cls ? 0 : 1;
        unsigned v = g_v[(size_t)b * KAn + j];
        unsigned V = g_thrV[b * 2 + c]; int cut = g_thrN[b * 2 + c];
        bool keep = (v < V) || (v == V && n <= cut);
        if (cls == 1) {
            if (keep) {
                label = 1.0f;
                unsigned long long key = g_key64[(size_t)b * KAn + j];
                int arg = 63 - (int)(key & 0xFFFFFFFFu);
                const float* gb = gt + (size_t)(b * Gn + arg) * 4;
                float gx1 = gb[0], gy1 = gb[1], gx2 = gb[2], gy2 = gb[3];
                float gw = __fadd_rn(__fsub_rn(gx2, gx1), 1.0f);
                float gh = __fadd_rn(__fsub_rn(gy2, gy1), 1.0f);
                float gcx = __fadd_rn(gx1, __fmul_rn(0.5f, __fsub_rn(gw, 1.0f)));
                float gcy = __fadd_rn(gy1, __fmul_rn(0.5f, __fsub_rn(gh, 1.0f)));
                float sx = (float)(ix << 4), sy = (float)(iy << 4);
                float aw = c_aw[a], ah = c_ah[a];
                float acx = __fadd_rn(__fadd_rn(c_ax1[a], sx), __fmul_rn(0.5f, __fsub_rn(aw, 1.0f)));
                float acy = __fadd_rn(__fadd_rn(c_ay1[a], sy), __fmul_rn(0.5f, __fsub_rn(ah, 1.0f)));
                t0 = __fdiv_rn(__fsub_rn(gcx, acx), aw);
                t1 = __fdiv_rn(__fsub_rn(gcy, acy), ah);
                t2 = logf(__fdiv_rn(gw, aw));
                t3 = logf(__fdiv_rn(gh, ah));
            }
        } else {
            label = keep ? 0.0f : -1.0f;
        }
    }
    out[(size_t)b * An * HWn + (size_t)a * HWn + r] = label;
    float* reg = out + (size_t)Bn * An * HWn;
    size_t rb = (size_t)b * An * 4 * HWn + (size_t)(a * 4) * HWn + r;
    reg[rb] = t0;
    reg[rb + HWn] = t1;
    reg[rb + 2 * HWn] = t2;
    reg[rb + 3 * HWn] = t3;
}

extern "C" void kernel_launch(void* const* d_in, const int* in_sizes, int n_in,
                              void* d_out, int out_size) {
    (void)in_sizes; (void)n_in; (void)out_size;
    const float* gt = (const float*)d_in[0];
    float* out = (float*)d_out;
    k_init<<<1, 256>>>();
    k_clear<<<(Bn * KAn) / 256, 256>>>();
    k_gtpass<<<Bn * Gn, 256>>>(gt);
    k_label<<<dim3(KAn / 256, Bn), 256>>>();
    k_select<<<Bn * 2, 1024>>>();
    k_final<<<dim3(KAn / 256, Bn), 256>>>(gt, out);
}

// round 5
// speedup vs baseline: 4.3264x; 1.3425x over previous
#include <cuda_runtime.h>
#include <cstdint>

#define JAX_PARTITIONABLE 1

#define Bn   32
#define Gn   50
#define Hn   64
#define Wn   64
#define An   9
#define HWn  4096
#define KAn  36864
#define NINn 18624
#define HALFN 9312
#define CAP  18624
#define CAPOV 7168

__constant__ int   c_ixmin[9]={6,11,23,4,8,16,3,5,11};
__constant__ int   c_ixmax[9]={57,52,40,59,55,47,60,58,52};
__constant__ int   c_iymin[9]={3,6,12,4,8,16,5,11,22};
__constant__ int   c_iymax[9]={60,57,51,59,55,47,58,52,41};
__constant__ float c_ax1[9]={-84.f,-176.f,-360.f,-56.f,-120.f,-248.f,-36.f,-80.f,-168.f};
__constant__ float c_ay1[9]={-40.f,-88.f,-184.f,-56.f,-120.f,-248.f,-80.f,-168.f,-344.f};
__constant__ float c_ax2[9]={99.f,191.f,375.f,71.f,135.f,263.f,51.f,95.f,183.f};
__constant__ float c_ay2[9]={55.f,103.f,199.f,71.f,135.f,263.f,95.f,183.f,359.f};
__constant__ float c_aw[9] ={184.f,368.f,736.f,128.f,256.f,512.f,88.f,176.f,352.f};
__constant__ float c_ah[9] ={96.f,192.f,384.f,128.f,256.f,512.f,176.f,352.f,704.f};
__constant__ float c_area[9]={17664.f,70656.f,282624.f,16384.f,65536.f,262144.f,15488.f,61952.f,247808.f};

// scratch
__device__ unsigned           g_keys[Bn][4];
__device__ unsigned long long g_key64[Bn*KAn];   // (ov_bits<<32)|(63-g)
__device__ unsigned char      g_hit[Bn*KAn];
__device__ unsigned char      g_cls[Bn*KAn];     // 0=bg,1=fg,2=ignore,3=outside
__device__ unsigned           g_v[Bn*KAn];       // 23-bit uniform payload, cls<2 only
__device__ unsigned short     g_nidx[KAn];       // compact index table (b-independent)
__device__ int                g_cnt[Bn*2];
__device__ unsigned           g_lv[Bn*2*CAP];
__device__ int                g_ln[Bn*2*CAP];
__device__ unsigned           g_thrV[Bn*2];
__device__ int                g_thrN[Bn*2];

// ---------------- Threefry-2x32 (bit-exact with jax) ----------------
__device__ __forceinline__ void tf2x32(unsigned k0, unsigned k1, unsigned x0, unsigned x1,
                                       unsigned& o0, unsigned& o1) {
    unsigned k2 = k0 ^ k1 ^ 0x1BD11BDAu;
    x0 += k0; x1 += k1;
#define TFR(r) { x0 += x1; x1 = (x1 << (r)) | (x1 >> (32 - (r))); x1 ^= x0; }
    TFR(13) TFR(15) TFR(26) TFR(6)   x0 += k1; x1 += k2 + 1u;
    TFR(17) TFR(29) TFR(16) TFR(24)  x0 += k2; x1 += k0 + 2u;
    TFR(13) TFR(15) TFR(26) TFR(6)   x0 += k0; x1 += k1 + 3u;
    TFR(17) TFR(29) TFR(16) TFR(24)  x0 += k1; x1 += k2 + 4u;
    TFR(13) TFR(15) TFR(26) TFR(6)   x0 += k2; x1 += k0 + 5u;
#undef TFR
    o0 = x0; o1 = x1;
}

__device__ __forceinline__ unsigned ubits(unsigned k0, unsigned k1, int n) {
#if JAX_PARTITIONABLE
    unsigned y0, y1;
    tf2x32(k0, k1, 0u, (unsigned)n, y0, y1);
    return y0 ^ y1;
#else
    unsigned y0, y1;
    if (n < HALFN) { tf2x32(k0, k1, (unsigned)n, (unsigned)(n + HALFN), y0, y1); return y0; }
    else           { tf2x32(k0, k1, (unsigned)(n - HALFN), (unsigned)n, y0, y1); return y1; }
#endif
}

__device__ __forceinline__ int compact_index(int iy, int ix, int a) {
    int n = 0;
#pragma unroll
    for (int j = 0; j < 9; j++) {
        int cy = min(iy, c_iymax[j] + 1) - c_iymin[j]; cy = max(cy, 0);
        int cx = c_ixmax[j] - c_ixmin[j] + 1;
        n += cy * cx;
        if (iy >= c_iymin[j] && iy <= c_iymax[j]) {
            int px = min(ix, c_ixmax[j] + 1) - c_ixmin[j]; px = max(px, 0);
            n += px;
            if (j < a && ix >= c_ixmin[j] && ix <= c_ixmax[j]) n += 1;
        }
    }
    return n;
}

__device__ __forceinline__ float iou_f(float ax1, float ay1, float ax2, float ay2, float areaa,
                                       float gx1, float gy1, float gx2, float gy2, float areag) {
    float iw = __fadd_rn(__fsub_rn(fminf(ax2, gx2), fmaxf(ax1, gx1)), 1.0f); iw = fmaxf(iw, 0.0f);
    float ih = __fadd_rn(__fsub_rn(fminf(ay2, gy2), fmaxf(ay1, gy1)), 1.0f); ih = fmaxf(ih, 0.0f);
    float inter = __fmul_rn(iw, ih);
    return __fdiv_rn(inter, __fsub_rn(__fadd_rn(areaa, areag), inter));
}

// ---------------- merged setup: clear + nidx table + keys ----------------
__global__ void __launch_bounds__(256) k_setup() {
    int i = blockIdx.x * 256 + threadIdx.x;
    g_key64[i] = 63ull;   // ov=0, arg=0
    g_hit[i] = 0;
    if (i < KAn) {
        int a = i / HWn; int r = i - a * HWn; int iy = r >> 6; int ix = r & 63;
        g_nidx[i] = (unsigned short)compact_index(iy, ix, a);
    }
    if (i < Bn) {
        unsigned f0, f1, q0, q1, b0, b1;
        tf2x32(0u, 42u, 0u, (unsigned)i, b0, b1);
        tf2x32(b0, b1, 0u, 0u, f0, f1);
        tf2x32(b0, b1, 0u, 1u, q0, q1);
        g_keys[i][0] = f0; g_keys[i][1] = f1; g_keys[i][2] = q0; g_keys[i][3] = q1;
    }
    if (i < Bn * 2) g_cnt[i] = 0;
}

// conservative window bounds for anchor type a vs gt box
__device__ __forceinline__ void win(int a, float gx1, float gy1, float gx2, float gy2,
                                    int& xlo, int& xhi, int& ylo, int& yhi) {
    xlo = max(c_ixmin[a], (int)floorf((gx1 - 1.0f - c_ax2[a]) * 0.0625f));
    xhi = min(c_ixmax[a], (int)ceilf((gx2 + 1.0f - c_ax1[a]) * 0.0625f));
    ylo = max(c_iymin[a], (int)floorf((gy1 - 1.0f - c_ay2[a]) * 0.0625f));
    yhi = min(c_iymax[a], (int)ceilf((gy2 + 1.0f - c_ay1[a]) * 0.0625f));
}

// one block per (b,g): pass A computes windowed IoUs (cached in smem) + atomicMax keys
// + block-max; pass B scans the cached IoUs to flag ov==gt_max hits.
__global__ void __launch_bounds__(256) k_gtpass(const float* __restrict__ gt) {
    __shared__ float sov[CAPOV];
    __shared__ float red[256];
    int blk = blockIdx.x;
    int b = blk / Gn, g = blk - b * Gn;
    const float* gb = gt + (size_t)(b * Gn + g) * 4;
    float gx1 = gb[0], gy1 = gb[1], gx2 = gb[2], gy2 = gb[3];
    float gw = __fadd_rn(__fsub_rn(gx2, gx1), 1.0f);
    float gh = __fadd_rn(__fsub_rn(gy2, gy1), 1.0f);
    float areag = __fmul_rn(gw, gh);
    float best = 0.0f;
    unsigned lowbits = (unsigned)(63 - g);

    int xlo9[9], ylo9[9], nx9[9], tot9[9], off9[9];
    int off = 0;
#pragma unroll
    for (int a = 0; a < 9; a++) {
        int xlo, xhi, ylo, yhi;
        win(a, gx1, gy1, gx2, gy2, xlo, xhi, ylo, yhi);
        int nx = xhi - xlo + 1, ny = yhi - ylo + 1;
        int tot = (nx > 0 && ny > 0) ? nx * ny : 0;
        xlo9[a] = xlo; ylo9[a] = ylo; nx9[a] = nx; tot9[a] = tot; off9[a] = off;
        off += tot;
    }
    bool cache = (off <= CAPOV);

#pragma unroll
    for (int a = 0; a < 9; a++) {
        int tot = tot9[a];
        if (tot == 0) continue;
        int xlo = xlo9[a], ylo = ylo9[a], nx = nx9[a], base = off9[a];
        float ax1 = c_ax1[a], ay1 = c_ay1[a], ax2 = c_ax2[a], ay2 = c_ay2[a], areaa = c_area[a];
        for (int t = threadIdx.x; t < tot; t += 256) {
            int q = t / nx;
            int iy = ylo + q, ix = xlo + t - q * nx;
            float sx = (float)(ix << 4), sy = (float)(iy << 4);
            float ov = iou_f(ax1 + sx, ay1 + sy, ax2 + sx, ay2 + sy, areaa,
                             gx1, gy1, gx2, gy2, areag);
            if (cache) sov[base + t] = ov;
            if (ov > 0.0f) {
                best = fmaxf(best, ov);
                unsigned long long key = ((unsigned long long)__float_as_uint(ov) << 32) | lowbits;
                atomicMax(&g_key64[(size_t)b * KAn + a * HWn + (iy << 6) + ix], key);
            }
        }
    }
    red[threadIdx.x] = best;
    __syncthreads();
    for (int s = 128; s > 0; s >>= 1) {
        if (threadIdx.x < s) red[threadIdx.x] = fmaxf(red[threadIdx.x], red[threadIdx.x + s]);
        __syncthreads();
    }
    float gm = red[0];
    if (gm <= 0.0f) return;
    // pass B: flag anchors achieving this gt's max overlap
#pragma unroll
    for (int a = 0; a < 9; a++) {
        int tot = tot9[a];
        if (tot == 0) continue;
        int xlo = xlo9[a], ylo = ylo9[a], nx = nx9[a], base = off9[a];
        float ax1 = c_ax1[a], ay1 = c_ay1[a], ax2 = c_ax2[a], ay2 = c_ay2[a], areaa = c_area[a];
        for (int t = threadIdx.x; t < tot; t += 256) {
            int q = t / nx;
            int iy = ylo + q, ix = xlo + t - q * nx;
            float ov;
            if (cache) {
                ov = sov[base + t];
            } else {
                float sx = (float)(ix << 4), sy = (float)(iy << 4);
                ov = iou_f(ax1 + sx, ay1 + sy, ax2 + sx, ay2 + sy, areaa,
                           gx1, gy1, gx2, gy2, areag);
            }
            if (ov == gm) g_hit[(size_t)b * KAn + a * HWn + (iy << 6) + ix] = 1;
        }
    }
}

__global__ void __launch_bounds__(256) k_label() {
    __shared__ int lcnt[2];
    __shared__ int lbase[2];
    int b = blockIdx.y;
    int t = threadIdx.x;
    if (t < 2) lcnt[t] = 0;
    __syncthreads();
    int j = blockIdx.x * 256 + t;       // a-major
    int a = j / HWn; int r = j - a * HWn; int iy = r >> 6; int ix = r & 63;
    unsigned char cls = 3;
    int c = 0, lp = 0, n = 0; unsigned v = 0;
    if (!(ix < c_ixmin[a] || ix > c_ixmax[a] || iy < c_iymin[a] || iy > c_iymax[a])) {
        unsigned long long key = g_key64[(size_t)b * KAn + j];
        float best = __uint_as_float((unsigned)(key >> 32));
        bool hit = g_hit[(size_t)b * KAn + j] != 0;
        cls = (hit || best >= 0.7f) ? (unsigned char)1
            : ((best < 0.3f) ? (unsigned char)0 : (unsigned char)2);
        if (cls < 2) {
            c = cls ? 0 : 1;
            n = g_nidx[j];
            v = ubits(g_keys[b][c * 2], g_keys[b][c * 2 + 1], n) >> 9;
            g_v[(size_t)b * KAn + j] = v;
            lp = atomicAdd(&lcnt[c], 1);
        }
    }
    g_cls[(size_t)b * KAn + j] = cls;
    __syncthreads();
    if (t < 2) lbase[t] = lcnt[t] ? atomicAdd(&g_cnt[b * 2 + t], lcnt[t]) : 0;
    __syncthreads();
    if (cls < 2) {
        int p = (b * 2 + c) * CAP + lbase[c] + lp;
        g_lv[p] = v;
        g_ln[p] = n;
    }
}

__device__ void find_kth(unsigned* hist, int per, unsigned k, unsigned* wsum,
                         int* s_bin, unsigned* s_below, int tid) {
    int base = tid * per;
    unsigned mysum = 0;
    for (int x = 0; x < per; x++) mysum += hist[base + x];
    unsigned lane = tid & 31, wid = tid >> 5;
    unsigned inc = mysum;
#pragma unroll
    for (int off = 1; off < 32; off <<= 1) {
        unsigned nv = __shfl_up_sync(0xffffffffu, inc, off);
        if (lane >= off) inc += nv;
    }
    if (lane == 31) wsum[wid] = inc;
    __syncthreads();
    if (wid == 0) {
        unsigned w = wsum[lane];
        unsigned iw = w;
#pragma unroll
        for (int off = 1; off < 32; off <<= 1) {
            unsigned nv = __shfl_up_sync(0xffffffffu, iw, off);
            if (lane >= off) iw += nv;
        }
        wsum[lane] = iw - w;
    }
    __syncthreads();
    unsigned run = wsum[wid] + (inc - mysum);
    for (int x = 0; x < per; x++) {
        unsigned h = hist[base + x];
        if (run < k && k <= run + h) { *s_bin = base + x; *s_below = run; }
        run += h;
    }
    __syncthreads();
}

__global__ void __launch_bounds__(1024) k_select() {
    __shared__ unsigned hist[4096];
    __shared__ unsigned wsum[32];
    __shared__ int s_bin; __shared__ unsigned s_below;
    __shared__ int s_list[4096]; __shared__ int s_cnt; __shared__ int s_cut;
    int bc = blockIdx.x; int b = bc >> 1; int c = bc & 1;
    int tid = threadIdx.x;
    int nfg = g_cnt[b * 2 + 0], nbg = g_cnt[b * 2 + 1];
    int m = c ? nbg : nfg;
    unsigned k = c ? (unsigned)(256 - min(nfg, 128)) : 128u;
    if ((unsigned)m <= k) {
        if (tid == 0) { g_thrV[bc] = 0xFFFFFFFFu; g_thrN[bc] = 0x7FFFFFFF; }
        return;
    }
    const unsigned* lv = g_lv + (size_t)bc * CAP;
    const int* ln = g_ln + (size_t)bc * CAP;

    for (int x = tid; x < 4096; x += 1024) hist[x] = 0;
    __syncthreads();
    for (int i = tid; i < m; i += 1024) atomicAdd(&hist[lv[i] >> 11], 1u);
    __syncthreads();
    find_kth(hist, 4, k, wsum, &s_bin, &s_below, tid);
    int T = s_bin; unsigned below1 = s_below;
    __syncthreads();

    for (int x = tid; x < 2048; x += 1024) hist[x] = 0;
    __syncthreads();
    for (int i = tid; i < m; i += 1024) {
        unsigned v = lv[i];
        if ((int)(v >> 11) == T) atomicAdd(&hist[v & 2047], 1u);
    }
    __syncthreads();
    find_kth(hist, 2, k - below1, wsum, &s_bin, &s_below, tid);
    unsigned V = ((unsigned)T << 11) | (unsigned)s_bin;
    unsigned cntLess = below1 + s_below;
    int R = (int)(k - cntLess);
    __syncthreads();

    if (tid == 0) { s_cnt = 0; s_cut = 0x7FFFFFFF; }
    __syncthreads();
    for (int i = tid; i < m; i += 1024) {
        if (lv[i] == V) { int p = atomicAdd(&s_cnt, 1); if (p < 4096) s_list[p] = ln[i]; }
    }
    __syncthreads();
    int E = min(s_cnt, 4096);
    if (R < E) {
        for (int e = tid; e < E; e += 1024) {
            int nv = s_list[e]; int rk = 0;
            for (int f = 0; f < E; f++) rk += (s_list[f] < nv);
            if (rk == R - 1) s_cut = nv;
        }
    }
    __syncthreads();
    if (tid == 0) { g_thrV[bc] = V; g_thrN[bc] = s_cut; }
}

__global__ void __launch_bounds__(256) k_final(const float* __restrict__ gt, float* __restrict__ out) {
    int b = blockIdx.y;
    int j = blockIdx.x * 256 + threadIdx.x;   // a-major
    int a = j / HWn; int r = j - a * HWn; int iy = r >> 6; int ix = r & 63;
    float label = -1.0f;
    float t0 = 0.f, t1 = 0.f, t2 = 0.f, t3 = 0.f;
    unsigned char cls = g_cls[(size_t)b * KAn + j];
    if (cls < 2) {
        int n = g_nidx[j];
        int c = cls ? 0 : 1;
        unsigned v = g_v[(size_t)b * KAn + j];
        unsigned V = g_thrV[b * 2 + c]; int cut = g_thrN[b * 2 + c];
        bool keep = (v < V) || (v == V && n <= cut);
        if (cls == 1) {
            if (keep) {
                label = 1.0f;
                unsigned long long key = g_key64[(size_t)b * KAn + j];
                int arg = 63 - (int)(key & 0xFFFFFFFFu);
                const float* gb = gt + (size_t)(b * Gn + arg) * 4;
                float gx1 = gb[0], gy1 = gb[1], gx2 = gb[2], gy2 = gb[3];
                float gw = __fadd_rn(__fsub_rn(gx2, gx1), 1.0f);
                float gh = __fadd_rn(__fsub_rn(gy2, gy1), 1.0f);
                float gcx = __fadd_rn(gx1, __fmul_rn(0.5f, __fsub_rn(gw, 1.0f)));
                float gcy = __fadd_rn(gy1, __fmul_rn(0.5f, __fsub_rn(gh, 1.0f)));
                float sx = (float)(ix << 4), sy = (float)(iy << 4);
                float aw = c_aw[a], ah = c_ah[a];
                float acx = __fadd_rn(__fadd_rn(c_ax1[a], sx), __fmul_rn(0.5f, __fsub_rn(aw, 1.0f)));
                float acy = __fadd_rn(__fadd_rn(c_ay1[a], sy), __fmul_rn(0.5f, __fsub_rn(ah, 1.0f)));
                t0 = __fdiv_rn(__fsub_rn(gcx, acx), aw);
                t1 = __fdiv_rn(__fsub_rn(gcy, acy), ah);
                t2 = logf(__fdiv_rn(gw, aw));
                t3 = logf(__fdiv_rn(gh, ah));
            }
        } else {
            label = keep ? 0.0f : -1.0f;
        }
    }
    out[(size_t)b * An * HWn + (size_t)a * HWn + r] = label;
    float* reg = out + (size_t)Bn * An * HWn;
    size_t rb = (size_t)b * An * 4 * HWn + (size_t)(a * 4) * HWn + r;
    reg[rb] = t0;
    reg[rb + HWn] = t1;
    reg[rb + 2 * HWn] = t2;
    reg[rb + 3 * HWn] = t3;
}

extern "C" void kernel_launch(void* const* d_in, const int* in_sizes, int n_in,
                              void* d_out, int out_size) {
    (void)in_sizes; (void)n_in; (void)out_size;
    const float* gt = (const float*)d_in[0];
    float* out = (float*)d_out;
    k_setup<<<(Bn * KAn) / 256, 256>>>();
    k_gtpass<<<Bn * Gn, 256>>>(gt);
    k_label<<<dim3(KAn / 256, Bn), 256>>>();
    k_select<<<Bn * 2, 1024>>>();
    k_final<<<dim3(KAn / 256, Bn), 256>>>(gt, out);
}